// round 5
// baseline (speedup 1.0000x reference)
#include <cuda_runtime.h>
#include <cuda_bf16.h>
#include <cstdint>
#include <math.h>

// Problem sizes
#define T_ 256
#define B_ 128
#define D_ 1024
#define H_ 1024
#define O_ 1024
// rows of big GEMM
#define MROWS (T_*B_)   // 32768
#define NCOLS (4*H_)    // 4096

// ---------------- device scratch (static, zero-init, no allocs) -------------
__device__ __align__(16) __nv_bfloat16 g_xbf[(size_t)MROWS * D_];        // 64MB
__device__ __align__(16) float         g_Zx[(size_t)MROWS * NCOLS];      // 512MB
__device__ __align__(16) uint2         g_Wxp[32u*64u*16u*32u];           // 8MB  [cn][kt][nt][lane]
__device__ __align__(16) uint2         g_Whp[128u*64u*4u*32u];           // 8MB  [ct][kt][g][lane]
__device__ float                       g_b4[NCOLS];
__device__ __align__(16) __nv_bfloat16 g_h[2][B_*H_];                    // ping-pong h (bf16)
__device__ __align__(16) float         g_hT[B_*H_];                      // final h fp32
__device__ unsigned g_barcnt;   // zero-init
__device__ unsigned g_bargen;   // zero-init

// ---------------- small PTX helpers ----------------
__device__ __forceinline__ void cpa16(uint32_t saddr, const void* gptr) {
    asm volatile("cp.async.cg.shared.global [%0], [%1], 16;" :: "r"(saddr), "l"(gptr));
}
__device__ __forceinline__ void cpa_commit() { asm volatile("cp.async.commit_group;"); }
__device__ __forceinline__ void cpa_wait0()  { asm volatile("cp.async.wait_group 0;"); }
__device__ __forceinline__ void cpa_wait1()  { asm volatile("cp.async.wait_group 1;"); }

__device__ __forceinline__ void ldsm_x4(uint32_t& r0, uint32_t& r1, uint32_t& r2, uint32_t& r3,
                                        uint32_t saddr) {
    asm volatile("ldmatrix.sync.aligned.m8n8.x4.shared.b16 {%0,%1,%2,%3}, [%4];"
                 : "=r"(r0), "=r"(r1), "=r"(r2), "=r"(r3) : "r"(saddr));
}
__device__ __forceinline__ void mma16816(float* d, const uint32_t* a, const uint2 b) {
    asm volatile("mma.sync.aligned.m16n8k16.row.col.f32.bf16.bf16.f32 "
                 "{%0,%1,%2,%3}, {%4,%5,%6,%7}, {%8,%9}, {%0,%1,%2,%3};"
                 : "+f"(d[0]), "+f"(d[1]), "+f"(d[2]), "+f"(d[3])
                 : "r"(a[0]), "r"(a[1]), "r"(a[2]), "r"(a[3]), "r"(b.x), "r"(b.y));
}
__device__ __forceinline__ uint32_t s2u(const void* p) {
    return (uint32_t)__cvta_generic_to_shared(p);
}
__device__ __forceinline__ uint32_t swz(uint32_t byte) {   // 128B swizzle
    return byte ^ ((byte >> 3) & 0x70u);
}

// ---------------- prep kernels ----------------
__global__ void k_cvt_x(const float* __restrict__ x) {
    size_t idx = (size_t)blockIdx.x * blockDim.x + threadIdx.x;   // 8388608 float4s
    if (idx >= (size_t)MROWS * D_ / 4) return;
    float4 v = reinterpret_cast<const float4*>(x)[idx];
    __nv_bfloat162* dst = reinterpret_cast<__nv_bfloat162*>(g_xbf);
    dst[idx * 2 + 0] = __floats2bfloat162_rn(v.x, v.y);
    dst[idx * 2 + 1] = __floats2bfloat162_rn(v.z, v.w);
}

__global__ void k_pack_wx(const float* Wf, const float* Wi, const float* Wg, const float* Wo) {
    unsigned id = blockIdx.x * blockDim.x + threadIdx.x;  // 1048576
    if (id >= 32u*64u*16u*32u) return;
    unsigned lane = id & 31u, nt = (id >> 5) & 15u, kt = (id >> 9) & 63u, cn = id >> 15;
    unsigned c = cn * 128u + nt * 8u + (lane >> 2);
    unsigned g = c >> 10, j = c & 1023u;
    unsigned k0 = kt * 16u + (lane & 3u) * 2u;
    const float* W = (g == 0) ? Wf : (g == 1) ? Wi : (g == 2) ? Wg : Wo;
    const float* base = W + (size_t)j * (D_ + H_) + k0;     // x-part: cols [0,1024)
    __nv_bfloat162 p0 = __floats2bfloat162_rn(base[0], base[1]);
    __nv_bfloat162 p1 = __floats2bfloat162_rn(base[8], base[9]);
    uint2 out;
    out.x = *reinterpret_cast<uint32_t*>(&p0);
    out.y = *reinterpret_cast<uint32_t*>(&p1);
    g_Wxp[id] = out;
}

__global__ void k_pack_wh(const float* Wf, const float* Wi, const float* Wg, const float* Wo) {
    unsigned id = blockIdx.x * blockDim.x + threadIdx.x;  // 1048576
    if (id >= 128u*64u*4u*32u) return;
    unsigned lane = id & 31u, g = (id >> 5) & 3u, kt = (id >> 7) & 63u, ct = id >> 13;
    unsigned j = ct * 8u + (lane >> 2);
    unsigned k0 = kt * 16u + (lane & 3u) * 2u;
    const float* W = (g == 0) ? Wf : (g == 1) ? Wi : (g == 2) ? Wg : Wo;
    const float* base = W + (size_t)j * (D_ + H_) + D_ + k0;  // h-part: cols [1024,2048)
    __nv_bfloat162 p0 = __floats2bfloat162_rn(base[0], base[1]);
    __nv_bfloat162 p1 = __floats2bfloat162_rn(base[8], base[9]);
    uint2 out;
    out.x = *reinterpret_cast<uint32_t*>(&p0);
    out.y = *reinterpret_cast<uint32_t*>(&p1);
    g_Whp[id] = out;
}

__global__ void k_pack_b(const float* bf, const float* bi, const float* bg, const float* bo) {
    unsigned i = blockIdx.x * blockDim.x + threadIdx.x;
    if (i >= NCOLS) return;
    unsigned g = i >> 10, j = i & 1023u;
    const float* b = (g == 0) ? bf : (g == 1) ? bi : (g == 2) ? bg : bo;
    g_b4[i] = b[j];
}

// ---------------- Phase A: Zx = xbf @ Wx4^T + b4 ----------------
// CTA tile 128x128, K chunks of 64. 8 warps: 2m x 4n, warp tile 64x32.
// smem: As[2][128*64]bf16 (2x16KB, swizzled) + Bs[2][4*16*32]uint2 (2x16KB)
__global__ void __launch_bounds__(256) k_gemmA() {
    extern __shared__ char sm[];
    char* As0 = sm;                 // 16KB each
    char* As1 = sm + 16384;
    uint2* Bs0 = reinterpret_cast<uint2*>(sm + 32768);
    uint2* Bs1 = reinterpret_cast<uint2*>(sm + 49152);
    const int tid = threadIdx.x, lane = tid & 31, w = tid >> 5;
    const int wm = w >> 2, wn = w & 3;
    const int cn = blockIdx.x;           // 0..31
    const int m0 = blockIdx.y * 128;     // 0..32640

    float acc[4][4][4];
#pragma unroll
    for (int a = 0; a < 4; a++)
#pragma unroll
        for (int b = 0; b < 4; b++)
#pragma unroll
            for (int c = 0; c < 4; c++) acc[a][b][c] = 0.f;

    auto load_chunk = [&](int kc, int buf) {
        char* A = buf ? As1 : As0;
        uint2* Bsm = buf ? Bs1 : Bs0;
#pragma unroll
        for (int i = 0; i < 4; i++) {
            int idx = tid + i * 256;
            int row = idx >> 3, seg = idx & 7;
            const void* src = &g_xbf[(size_t)(m0 + row) * D_ + kc * 64 + seg * 8];
            cpa16(s2u(A + swz(row * 128 + seg * 16)), src);
        }
        const uint4* bsrc = reinterpret_cast<const uint4*>(&g_Wxp[((size_t)cn * 64 + kc * 4) * 16 * 32]);
        uint4* bdst = reinterpret_cast<uint4*>(Bsm);
#pragma unroll
        for (int i = 0; i < 4; i++) {
            int idx = tid + i * 256;  // 1024 x 16B
            cpa16(s2u(bdst + idx), bsrc + idx);
        }
        cpa_commit();
    };

    load_chunk(0, 0);
    for (int kc = 0; kc < 16; kc++) {
        int buf = kc & 1;
        if (kc < 15) load_chunk(kc + 1, buf ^ 1);
        if (kc < 15) cpa_wait1(); else cpa_wait0();
        __syncthreads();
        char* A = buf ? As1 : As0;
        uint2* Bsm = buf ? Bs1 : Bs0;
#pragma unroll
        for (int ktl = 0; ktl < 4; ktl++) {
            uint32_t afr[4][4];
#pragma unroll
            for (int mt = 0; mt < 4; mt++) {
                int r = wm * 64 + mt * 16 + (lane & 15);
                int ch = ktl * 16 + ((lane >> 4) << 3);
                ldsm_x4(afr[mt][0], afr[mt][1], afr[mt][2], afr[mt][3],
                        s2u(A + swz(r * 128 + ch * 2)));
            }
            uint2 bfr[4];
#pragma unroll
            for (int nt = 0; nt < 4; nt++)
                bfr[nt] = Bsm[((ktl) * 16 + wn * 4 + nt) * 32 + lane];
#pragma unroll
            for (int mt = 0; mt < 4; mt++)
#pragma unroll
                for (int nt = 0; nt < 4; nt++)
                    mma16816(acc[mt][nt], afr[mt], bfr[nt]);
        }
        __syncthreads();
    }
    // epilogue: add bias, write fp32
#pragma unroll
    for (int mt = 0; mt < 4; mt++) {
        int r0 = m0 + wm * 64 + mt * 16 + (lane >> 2);
#pragma unroll
        for (int nt = 0; nt < 4; nt++) {
            int c0 = cn * 128 + wn * 32 + nt * 8 + (lane & 3) * 2;
            float b0 = g_b4[c0], b1 = g_b4[c0 + 1];
            float2 v0 = make_float2(acc[mt][nt][0] + b0, acc[mt][nt][1] + b1);
            float2 v1 = make_float2(acc[mt][nt][2] + b0, acc[mt][nt][3] + b1);
            *reinterpret_cast<float2*>(&g_Zx[(size_t)r0 * NCOLS + c0]) = v0;
            *reinterpret_cast<float2*>(&g_Zx[(size_t)(r0 + 8) * NCOLS + c0]) = v1;
        }
    }
}

// ---------------- Phase B: persistent recurrent kernel ----------------
// 128 CTAs. CTA ct owns hidden units [ct*8, ct*8+8) x 4 gates x 128 batches.
// smem: WhS 64KB parked + As[2][128*64]bf16 (32KB) + zs[128*32]f32 (16KB)
__global__ void __launch_bounds__(256) k_lstm() {
    extern __shared__ char sm[];
    uint2* WhS = reinterpret_cast<uint2*>(sm);          // [64][4][32] uint2 = 64KB
    char* As0 = sm + 65536;
    char* As1 = sm + 65536 + 16384;
    float* zs = reinterpret_cast<float*>(sm + 65536 + 32768);   // [128][32]
    const int ct = blockIdx.x;
    const int tid = threadIdx.x, lane = tid & 31, w = tid >> 5;
    const int wm = w >> 2, wn = w & 3;   // wn == gate

    // park Wh fragments (64KB contiguous)
    {
        const uint4* src = reinterpret_cast<const uint4*>(&g_Whp[(size_t)ct * 64 * 4 * 32]);
        uint4* dst = reinterpret_cast<uint4*>(WhS);
        for (int i = tid; i < 4096; i += 256) dst[i] = src[i];
    }
    float cst[4] = {0.f, 0.f, 0.f, 0.f};
    __syncthreads();

    for (int t = 0; t < T_; t++) {
        // prefetch Zx for this CTA's cells
        float zx[4][4];
#pragma unroll
        for (int i = 0; i < 4; i++) {
            int cell = tid + i * 256;
            int b = cell >> 3, jl = cell & 7;
            const float* zp = &g_Zx[(size_t)(t * B_ + b) * NCOLS + ct * 8 + jl];
            zx[i][0] = zp[0]; zx[i][1] = zp[1024]; zx[i][2] = zp[2048]; zx[i][3] = zp[3072];
        }
        float acc[4][4];
#pragma unroll
        for (int a = 0; a < 4; a++)
#pragma unroll
            for (int b = 0; b < 4; b++) acc[a][b] = 0.f;

        if (t > 0) {
            const __nv_bfloat16* hsrc = g_h[(t + 1) & 1];
            auto load_chunk = [&](int kc, int buf) {
                char* A = buf ? As1 : As0;
#pragma unroll
                for (int i = 0; i < 4; i++) {
                    int idx = tid + i * 256;
                    int row = idx >> 3, seg = idx & 7;
                    const void* src = &hsrc[(size_t)row * H_ + kc * 64 + seg * 8];
                    cpa16(s2u(A + swz(row * 128 + seg * 16)), src);
                }
                cpa_commit();
            };
            load_chunk(0, 0);
            for (int kc = 0; kc < 16; kc++) {
                int buf = kc & 1;
                if (kc < 15) load_chunk(kc + 1, buf ^ 1);
                if (kc < 15) cpa_wait1(); else cpa_wait0();
                __syncthreads();
                char* A = buf ? As1 : As0;
#pragma unroll
                for (int ktl = 0; ktl < 4; ktl++) {
                    uint2 bfr = WhS[((kc * 4 + ktl) * 4 + wn) * 32 + lane];
#pragma unroll
                    for (int mt = 0; mt < 4; mt++) {
                        int r = wm * 64 + mt * 16 + (lane & 15);
                        int ch = ktl * 16 + ((lane >> 4) << 3);
                        uint32_t afr[4];
                        ldsm_x4(afr[0], afr[1], afr[2], afr[3],
                                s2u(A + swz(r * 128 + ch * 2)));
                        mma16816(acc[mt], afr, bfr);
                    }
                }
                __syncthreads();
            }
        }
        // write z tile to smem
#pragma unroll
        for (int mt = 0; mt < 4; mt++) {
            int r = wm * 64 + mt * 16 + (lane >> 2);
            int cl = wn * 8 + (lane & 3) * 2;
            zs[r * 32 + cl] = acc[mt][0];
            zs[r * 32 + cl + 1] = acc[mt][1];
            zs[(r + 8) * 32 + cl] = acc[mt][2];
            zs[(r + 8) * 32 + cl + 1] = acc[mt][3];
        }
        __syncthreads();
        // gate math + h write
        __nv_bfloat16* hdst = g_h[t & 1];
#pragma unroll
        for (int i = 0; i < 4; i++) {
            int cell = tid + i * 256;
            int b = cell >> 3, jl = cell & 7;
            float zi = zs[b * 32 + 0 + jl] + zx[i][0];
            float zf = zs[b * 32 + 8 + jl] + zx[i][1];
            float zg = zs[b * 32 + 16 + jl] + zx[i][2];
            float zo = zs[b * 32 + 24 + jl] + zx[i][3];
            float it = 1.f / (1.f + expf(-zi));
            float ft = 1.f / (1.f + expf(-zf));
            float gt = tanhf(zg);
            float ot = 1.f / (1.f + expf(-zo));
            cst[i] = ft * cst[i] + it * gt;
            float hh = ot * tanhf(cst[i]);
            hdst[(size_t)b * H_ + ct * 8 + jl] = __float2bfloat16(hh);
            if (t == T_ - 1) g_hT[(size_t)b * H_ + ct * 8 + jl] = hh;
        }
        __syncthreads();
        __threadfence();
        // grid barrier
        if (tid == 0) {
            unsigned gen = atomicAdd(&g_bargen, 0u);
            unsigned r = atomicAdd(&g_barcnt, 1u);
            if (r == (unsigned)(gridDim.x - 1)) {
                atomicExch(&g_barcnt, 0u);
                __threadfence();
                atomicAdd(&g_bargen, 1u);
            } else {
                while (atomicAdd(&g_bargen, 0u) == gen) __nanosleep(64);
            }
            __threadfence();
        }
        __syncthreads();
    }
}

// ---------------- Phase C: logits + log_softmax ----------------
__global__ void __launch_bounds__(256) k_logits(const float* __restrict__ Wout,
                                                const float* __restrict__ bout,
                                                float* __restrict__ out) {
    __shared__ float hs[1024];
    __shared__ float ls[1024];
    __shared__ float red[16];
    const int b = blockIdx.x, tid = threadIdx.x, lane = tid & 31, w = tid >> 5;
    for (int i = tid; i < 1024; i += 256) hs[i] = g_hT[(size_t)b * H_ + i];
    __syncthreads();
    for (int k = 0; k < 4; k++) {
        int o = tid + k * 256;
        const float4* wr = reinterpret_cast<const float4*>(Wout + (size_t)o * H_);
        float s = 0.f;
#pragma unroll 4
        for (int h4 = 0; h4 < 256; h4++) {
            float4 wv = wr[h4];
            s += hs[h4 * 4 + 0] * wv.x + hs[h4 * 4 + 1] * wv.y +
                 hs[h4 * 4 + 2] * wv.z + hs[h4 * 4 + 3] * wv.w;
        }
        ls[o] = s + bout[o];
    }
    __syncthreads();
    float lm = -1e30f;
    for (int i = tid; i < 1024; i += 256) lm = fmaxf(lm, ls[i]);
#pragma unroll
    for (int off = 16; off; off >>= 1) lm = fmaxf(lm, __shfl_xor_sync(0xffffffffu, lm, off));
    if (lane == 0) red[w] = lm;
    __syncthreads();
    float m = red[0];
#pragma unroll
    for (int j = 1; j < 8; j++) m = fmaxf(m, red[j]);
    float se = 0.f;
    for (int i = tid; i < 1024; i += 256) se += expf(ls[i] - m);
#pragma unroll
    for (int off = 16; off; off >>= 1) se += __shfl_xor_sync(0xffffffffu, se, off);
    if (lane == 0) red[8 + w] = se;
    __syncthreads();
    float tot = 0.f;
#pragma unroll
    for (int j = 0; j < 8; j++) tot += red[8 + j];
    float lse = logf(tot);
    for (int i = tid; i < 1024; i += 256)
        out[(size_t)b * O_ + i] = ls[i] - m - lse;
}

// ---------------- launch ----------------
extern "C" void kernel_launch(void* const* d_in, const int* in_sizes, int n_in,
                              void* d_out, int out_size) {
    const float* x    = (const float*)d_in[0];
    const float* Wf   = (const float*)d_in[1];
    const float* bf   = (const float*)d_in[2];
    const float* Wi   = (const float*)d_in[3];
    const float* bi   = (const float*)d_in[4];
    const float* Wg   = (const float*)d_in[5];
    const float* bg   = (const float*)d_in[6];
    const float* Wo   = (const float*)d_in[7];
    const float* bo   = (const float*)d_in[8];
    const float* Wout = (const float*)d_in[9];
    const float* bout = (const float*)d_in[10];
    float* out = (float*)d_out;

    cudaFuncSetAttribute(k_gemmA, cudaFuncAttributeMaxDynamicSharedMemorySize, 65536);
    cudaFuncSetAttribute(k_lstm,  cudaFuncAttributeMaxDynamicSharedMemorySize, 65536 + 32768 + 16384);

    k_cvt_x<<<(MROWS * D_ / 4 + 511) / 512, 512>>>(x);
    k_pack_wx<<<(32 * 64 * 16 * 32) / 256, 256>>>(Wf, Wi, Wg, Wo);
    k_pack_wh<<<(128 * 64 * 4 * 32) / 256, 256>>>(Wf, Wi, Wg, Wo);
    k_pack_b<<<NCOLS / 256, 256>>>(bf, bi, bg, bo);
    dim3 gA(32, 256);
    k_gemmA<<<gA, 256, 65536>>>();
    k_lstm<<<128, 256, 65536 + 32768 + 16384>>>();
    k_logits<<<B_, 256>>>(Wout, bout, out);
}